// round 2
// baseline (speedup 1.0000x reference)
#include <cuda_runtime.h>

#define NSITES 16
#define KDIM   256
#define EPSF   1e-10f

// One CTA per batch element. 4 warps:
//   Phase 1 (Gram blocks): warp0/1 -> M8 rows 0-3 / 4-7; warp2 -> ML; warp3 -> MR.
//   Phase 2 (Jacobi SVD + entropy): warp0 -> 8x8, warp1 -> both 4x4s.
__global__ __launch_bounds__(128, 4)
void phi_q_kernel(const float* __restrict__ sites, float* __restrict__ out) {
    const int b    = blockIdx.x;
    const int tid  = threadIdx.x;
    const int warp = tid >> 5;
    const int lane = tid & 31;
    const float* S = sites + (size_t)b * (NSITES * KDIM);

    __shared__ float M8[8][9];   // padded rows: bank-friendly column access
    __shared__ float ML[4][5];
    __shared__ float MR[4][5];
    __shared__ float Hs[3];

    // ---------------- Phase 1: cross-Gram blocks ----------------
    // Lane l owns k in {l, l+32, ..., l+224}: coalesced LDG, conflict-free.
    if (warp < 2) {
        // M8[i][j] = row_i . row_{8+j}; this warp does i = warp*4 .. warp*4+3
        float Br[8][8];
        #pragma unroll
        for (int j = 0; j < 8; j++)
            #pragma unroll
            for (int i = 0; i < 8; i++)
                Br[j][i] = S[(8 + j) * KDIM + lane + 32 * i];

        float acc[4][8];
        #pragma unroll
        for (int a = 0; a < 4; a++) {
            float Ar[8];
            #pragma unroll
            for (int i = 0; i < 8; i++)
                Ar[i] = S[(warp * 4 + a) * KDIM + lane + 32 * i];
            #pragma unroll
            for (int j = 0; j < 8; j++) {
                float s = 0.f;
                #pragma unroll
                for (int i = 0; i < 8; i++) s = fmaf(Ar[i], Br[j][i], s);
                acc[a][j] = s;
            }
        }
        #pragma unroll
        for (int a = 0; a < 4; a++)
            #pragma unroll
            for (int j = 0; j < 8; j++) {
                float v = acc[a][j];
                #pragma unroll
                for (int m = 16; m >= 1; m >>= 1)
                    v += __shfl_xor_sync(0xffffffffu, v, m);
                acc[a][j] = v;
            }
        if (lane == 0) {
            #pragma unroll
            for (int a = 0; a < 4; a++)
                #pragma unroll
                for (int j = 0; j < 8; j++)
                    M8[warp * 4 + a][j] = acc[a][j];
        }
    } else {
        // warp2: ML[i][j] = row_i . row_{4+j}; warp3: MR[i][j] = row_{8+i} . row_{12+j}
        const int r0 = (warp == 2) ? 0 : 8;
        float Br[4][8];
        #pragma unroll
        for (int j = 0; j < 4; j++)
            #pragma unroll
            for (int i = 0; i < 8; i++)
                Br[j][i] = S[(r0 + 4 + j) * KDIM + lane + 32 * i];

        float acc[4][4];
        #pragma unroll
        for (int a = 0; a < 4; a++) {
            float Ar[8];
            #pragma unroll
            for (int i = 0; i < 8; i++)
                Ar[i] = S[(r0 + a) * KDIM + lane + 32 * i];
            #pragma unroll
            for (int j = 0; j < 4; j++) {
                float s = 0.f;
                #pragma unroll
                for (int i = 0; i < 8; i++) s = fmaf(Ar[i], Br[j][i], s);
                acc[a][j] = s;
            }
        }
        #pragma unroll
        for (int a = 0; a < 4; a++)
            #pragma unroll
            for (int j = 0; j < 4; j++) {
                float v = acc[a][j];
                #pragma unroll
                for (int m = 16; m >= 1; m >>= 1)
                    v += __shfl_xor_sync(0xffffffffu, v, m);
                acc[a][j] = v;
            }
        if (lane == 0) {
            if (warp == 2) {
                #pragma unroll
                for (int a = 0; a < 4; a++)
                    #pragma unroll
                    for (int j = 0; j < 4; j++) ML[a][j] = acc[a][j];
            } else {
                #pragma unroll
                for (int a = 0; a < 4; a++)
                    #pragma unroll
                    for (int j = 0; j < 4; j++) MR[a][j] = acc[a][j];
            }
        }
    }
    __syncthreads();

    // ---------------- Phase 2: one-sided Jacobi + entropy ----------------
    // Right rotations keep singular values exactly invariant; at convergence
    // column-norm^2 = s^2. Entropy of p = (s^2+eps)/sum matches the reference.
    if (warp == 0) {
        // 8x8: 4 parallel pair-groups of 8 lanes. Tournament ordering:
        // round rr: g0 -> (7, rr); g>0 -> ((rr+g)%7, (rr+7-g)%7)
        const int g = lane >> 3, r = lane & 7;
        for (int sweep = 0; sweep < 8; sweep++) {
            for (int rr = 0; rr < 7; rr++) {
                int p, q;
                if (g == 0) { p = 7; q = rr; }
                else        { p = (rr + g) % 7; q = (rr + 7 - g) % 7; }
                float u = M8[r][p], w = M8[r][q];
                float al = u * u, be = w * w, ga = u * w;
                #pragma unroll
                for (int m = 4; m >= 1; m >>= 1) {
                    al += __shfl_xor_sync(0xffffffffu, al, m);
                    be += __shfl_xor_sync(0xffffffffu, be, m);
                    ga += __shfl_xor_sync(0xffffffffu, ga, m);
                }
                if (fabsf(ga) > 1e-20f) {
                    float tau = (be - al) / (2.f * ga);
                    float t = copysignf(1.f, tau) / (fabsf(tau) + sqrtf(1.f + tau * tau));
                    float c = rsqrtf(1.f + t * t);
                    float s = c * t;
                    M8[r][p] = c * u - s * w;
                    M8[r][q] = s * u + c * w;
                }
                __syncwarp();
            }
        }
        // entropy over 8 column norms^2
        const int j = lane & 7;
        float sq = EPSF;
        #pragma unroll
        for (int rr = 0; rr < 8; rr++) {
            float v = M8[rr][j];
            sq = fmaf(v, v, sq);
        }
        float T = sq;
        #pragma unroll
        for (int m = 4; m >= 1; m >>= 1) T += __shfl_xor_sync(0xffffffffu, T, m);
        float pj = sq / T;
        float term = pj * logf(pj + EPSF);
        #pragma unroll
        for (int m = 4; m >= 1; m >>= 1) term += __shfl_xor_sync(0xffffffffu, term, m);
        if (lane == 0) Hs[0] = -term;
    } else if (warp == 1) {
        // Both 4x4s in one warp. Lanes 0-15 do real work; lanes 16-31 are exact
        // duplicates (same reads, same values, same writes) to keep sync simple.
        const int mat = (lane >> 3) & 1;       // 0 -> ML, 1 -> MR
        const int g   = (lane >> 2) & 1;
        const int r   = lane & 3;
        float (*M)[5] = mat ? MR : ML;
        for (int sweep = 0; sweep < 6; sweep++) {
            for (int rr = 0; rr < 3; rr++) {
                int p, q;
                if (g == 0) { p = 3; q = rr; }
                else        { p = (rr + 1) % 3; q = (rr + 2) % 3; }
                float u = M[r][p], w = M[r][q];
                float al = u * u, be = w * w, ga = u * w;
                #pragma unroll
                for (int m = 2; m >= 1; m >>= 1) {
                    al += __shfl_xor_sync(0xffffffffu, al, m);
                    be += __shfl_xor_sync(0xffffffffu, be, m);
                    ga += __shfl_xor_sync(0xffffffffu, ga, m);
                }
                if (fabsf(ga) > 1e-20f) {
                    float tau = (be - al) / (2.f * ga);
                    float t = copysignf(1.f, tau) / (fabsf(tau) + sqrtf(1.f + tau * tau));
                    float c = rsqrtf(1.f + t * t);
                    float s = c * t;
                    M[r][p] = c * u - s * w;
                    M[r][q] = s * u + c * w;
                }
                __syncwarp();
            }
        }
        const int j = lane & 3;
        float sq = EPSF;
        #pragma unroll
        for (int rr = 0; rr < 4; rr++) {
            float v = M[rr][j];
            sq = fmaf(v, v, sq);
        }
        float T = sq;
        #pragma unroll
        for (int m = 2; m >= 1; m >>= 1) T += __shfl_xor_sync(0xffffffffu, T, m);
        float pj = sq / T;
        float term = pj * logf(pj + EPSF);
        #pragma unroll
        for (int m = 2; m >= 1; m >>= 1) term += __shfl_xor_sync(0xffffffffu, term, m);
        if (lane == 0) Hs[1] = -term;
        if (lane == 8) Hs[2] = -term;
    }
    __syncthreads();

    if (tid == 0) {
        float phi = Hs[0] - Hs[1] - Hs[2];
        out[b] = phi > 0.f ? phi : 0.f;
    }
}

extern "C" void kernel_launch(void* const* d_in, const int* in_sizes, int n_in,
                              void* d_out, int out_size) {
    const float* sites = (const float*)d_in[0];
    float* out = (float*)d_out;
    const int batch = out_size;   // 8192
    phi_q_kernel<<<batch, 128>>>(sites, out);
}

// round 3
// speedup vs baseline: 3.4769x; 3.4769x over previous
#include <cuda_runtime.h>

#define BATCH   8192
#define KDIM    256
#define EPSF    1e-10f
#define SW8     5      // Jacobi sweeps for 8x8
#define SW4     4      // Jacobi sweeps for 4x4

// Scratch: 96 Gram entries per element, transposed [96][BATCH] for coalesced k2 reads.
// idx 0..63  -> M8[i][j] = dot(row i,   row 8+j)   (i*8+j)
// idx 64..79 -> ML[i][j] = dot(row i,   row 4+j)   (64 + i*4+j)
// idx 80..95 -> MR[i][j] = dot(row 8+i, row 12+j)  (80 + i*4+j)
__device__ float g_scratch[96 * BATCH];

// ---------------------------------------------------------------------------
// Kernel 1: cross-Gram blocks. One CTA per element, S staged in smem once.
// ---------------------------------------------------------------------------
__global__ __launch_bounds__(128)
void gram_kernel(const float* __restrict__ sites) {
    const int b    = blockIdx.x;
    const int tid  = threadIdx.x;
    const int warp = tid >> 5;
    const int lane = tid & 31;

    __shared__ float sm[16 * KDIM];   // 16KB

    // Cooperative coalesced load: 4096 floats = 1024 float4, 8 per thread.
    {
        const float4* S4 = (const float4*)(sites + (size_t)b * (16 * KDIM));
        float4* sm4 = (float4*)sm;
        #pragma unroll
        for (int i = 0; i < 8; i++) sm4[tid + 128 * i] = S4[tid + 128 * i];
    }
    __syncthreads();

    // Lane l owns k in {l, l+32, ..., l+224}.
    if (warp < 2) {
        // M8 rows: warp0 -> i=0..3, warp1 -> i=4..7
        float Ar[4][8];
        #pragma unroll
        for (int a = 0; a < 4; a++)
            #pragma unroll
            for (int i = 0; i < 8; i++)
                Ar[a][i] = sm[(warp * 4 + a) * KDIM + lane + 32 * i];

        float acc[4][8];
        #pragma unroll
        for (int j = 0; j < 8; j++) {
            float Bj[8];
            #pragma unroll
            for (int i = 0; i < 8; i++)
                Bj[i] = sm[(8 + j) * KDIM + lane + 32 * i];
            #pragma unroll
            for (int a = 0; a < 4; a++) {
                float s = 0.f;
                #pragma unroll
                for (int i = 0; i < 8; i++) s = fmaf(Ar[a][i], Bj[i], s);
                acc[a][j] = s;
            }
        }
        #pragma unroll
        for (int a = 0; a < 4; a++)
            #pragma unroll
            for (int j = 0; j < 8; j++) {
                float v = acc[a][j];
                #pragma unroll
                for (int m = 16; m >= 1; m >>= 1)
                    v += __shfl_xor_sync(0xffffffffu, v, m);
                acc[a][j] = v;
            }
        if (lane == 0) {
            #pragma unroll
            for (int a = 0; a < 4; a++)
                #pragma unroll
                for (int j = 0; j < 8; j++)
                    g_scratch[((warp * 4 + a) * 8 + j) * BATCH + b] = acc[a][j];
        }
    } else {
        // warp2: ML (A rows 0..3, B rows 4..7); warp3: MR (A rows 8..11, B rows 12..15)
        const int ra = (warp == 2) ? 0 : 8;
        const int base = (warp == 2) ? 64 : 80;

        float Ar[4][8];
        #pragma unroll
        for (int a = 0; a < 4; a++)
            #pragma unroll
            for (int i = 0; i < 8; i++)
                Ar[a][i] = sm[(ra + a) * KDIM + lane + 32 * i];

        float acc[4][4];
        #pragma unroll
        for (int j = 0; j < 4; j++) {
            float Bj[8];
            #pragma unroll
            for (int i = 0; i < 8; i++)
                Bj[i] = sm[(ra + 4 + j) * KDIM + lane + 32 * i];
            #pragma unroll
            for (int a = 0; a < 4; a++) {
                float s = 0.f;
                #pragma unroll
                for (int i = 0; i < 8; i++) s = fmaf(Ar[a][i], Bj[i], s);
                acc[a][j] = s;
            }
        }
        #pragma unroll
        for (int a = 0; a < 4; a++)
            #pragma unroll
            for (int j = 0; j < 4; j++) {
                float v = acc[a][j];
                #pragma unroll
                for (int m = 16; m >= 1; m >>= 1)
                    v += __shfl_xor_sync(0xffffffffu, v, m);
                acc[a][j] = v;
            }
        if (lane == 0) {
            #pragma unroll
            for (int a = 0; a < 4; a++)
                #pragma unroll
                for (int j = 0; j < 4; j++)
                    g_scratch[(base + a * 4 + j) * BATCH + b] = acc[a][j];
        }
    }
}

// ---------------------------------------------------------------------------
// Kernel 2: per-thread one-sided Jacobi SVD (columns) + entropy, all registers.
// Branchless rotations; static indexing only (no spills).
// ---------------------------------------------------------------------------
__device__ __forceinline__ void rot_cols8(float A[8][8], int p, int q) {
    float al = 0.f, be = 0.f, ga = 0.f;
    #pragma unroll
    for (int r = 0; r < 8; r++) {
        float u = A[r][p], w = A[r][q];
        al = fmaf(u, u, al); be = fmaf(w, w, be); ga = fmaf(u, w, ga);
    }
    float tau = (be - al) * __fdividef(0.5f, ga);
    float t = copysignf(1.f, tau) *
              __fdividef(1.f, fabsf(tau) + sqrtf(fmaf(tau, tau, 1.f)));
    t = (fabsf(ga) > 1e-30f) ? t : 0.f;
    float c = rsqrtf(fmaf(t, t, 1.f));
    float sn = c * t;
    #pragma unroll
    for (int r = 0; r < 8; r++) {
        float u = A[r][p], w = A[r][q];
        A[r][p] = fmaf(c, u, -sn * w);
        A[r][q] = fmaf(sn, u, c * w);
    }
}

__device__ __forceinline__ void rot_cols4(float A[4][4], int p, int q) {
    float al = 0.f, be = 0.f, ga = 0.f;
    #pragma unroll
    for (int r = 0; r < 4; r++) {
        float u = A[r][p], w = A[r][q];
        al = fmaf(u, u, al); be = fmaf(w, w, be); ga = fmaf(u, w, ga);
    }
    float tau = (be - al) * __fdividef(0.5f, ga);
    float t = copysignf(1.f, tau) *
              __fdividef(1.f, fabsf(tau) + sqrtf(fmaf(tau, tau, 1.f)));
    t = (fabsf(ga) > 1e-30f) ? t : 0.f;
    float c = rsqrtf(fmaf(t, t, 1.f));
    float sn = c * t;
    #pragma unroll
    for (int r = 0; r < 4; r++) {
        float u = A[r][p], w = A[r][q];
        A[r][p] = fmaf(c, u, -sn * w);
        A[r][q] = fmaf(sn, u, c * w);
    }
}

__device__ __forceinline__ float entropy4(int base, int b) {
    float A[4][4];
    #pragma unroll
    for (int i = 0; i < 4; i++)
        #pragma unroll
        for (int j = 0; j < 4; j++)
            A[i][j] = g_scratch[(base + i * 4 + j) * BATCH + b];

    for (int s = 0; s < SW4; s++) {
        #pragma unroll
        for (int p = 0; p < 3; p++)
            #pragma unroll
            for (int q = p + 1; q < 4; q++)
                rot_cols4(A, p, q);
    }
    float sq[4], T = 0.f;
    #pragma unroll
    for (int j = 0; j < 4; j++) {
        float v = EPSF;
        #pragma unroll
        for (int r = 0; r < 4; r++) v = fmaf(A[r][j], A[r][j], v);
        sq[j] = v; T += v;
    }
    float invT = __fdividef(1.f, T);
    float H = 0.f;
    #pragma unroll
    for (int j = 0; j < 4; j++) {
        float pj = sq[j] * invT;
        H = fmaf(pj, __logf(pj + EPSF), H);
    }
    return -H;
}

__global__ __launch_bounds__(128)
void jacobi_kernel(float* __restrict__ out) {
    const int b = blockIdx.x * 128 + threadIdx.x;

    // ---- 8x8 whole-system entropy ----
    float A[8][8];
    #pragma unroll
    for (int i = 0; i < 8; i++)
        #pragma unroll
        for (int j = 0; j < 8; j++)
            A[i][j] = g_scratch[(i * 8 + j) * BATCH + b];

    for (int s = 0; s < SW8; s++) {
        #pragma unroll
        for (int p = 0; p < 7; p++)
            #pragma unroll
            for (int q = p + 1; q < 8; q++)
                rot_cols8(A, p, q);
    }
    float sq[8], T = 0.f;
    #pragma unroll
    for (int j = 0; j < 8; j++) {
        float v = EPSF;
        #pragma unroll
        for (int r = 0; r < 8; r++) v = fmaf(A[r][j], A[r][j], v);
        sq[j] = v; T += v;
    }
    float invT = __fdividef(1.f, T);
    float H0 = 0.f;
    #pragma unroll
    for (int j = 0; j < 8; j++) {
        float pj = sq[j] * invT;
        H0 = fmaf(pj, __logf(pj + EPSF), H0);
    }
    H0 = -H0;

    // ---- 4x4 halves ----
    float H1 = entropy4(64, b);
    float H2 = entropy4(80, b);

    float phi = H0 - H1 - H2;
    out[b] = phi > 0.f ? phi : 0.f;
}

extern "C" void kernel_launch(void* const* d_in, const int* in_sizes, int n_in,
                              void* d_out, int out_size) {
    const float* sites = (const float*)d_in[0];
    float* out = (float*)d_out;
    gram_kernel<<<BATCH, 128>>>(sites);
    jacobi_kernel<<<BATCH / 128, 128>>>(out);
}

// round 5
// speedup vs baseline: 4.0408x; 1.1622x over previous
#include <cuda_runtime.h>

#define BATCH   8192
#define KDIM    256
#define EPSF    1e-10f
#define SW8     5
#define SW4     4

// Scratch, transposed [96][BATCH]:
// 0..63  -> M8[i][j] = dot(row i,   row 8+j)
// 64..79 -> ML[i][j] = dot(row i,   row 4+j)
// 80..95 -> MR[i][j] = dot(row 8+i, row 12+j)
__device__ float g_scratch[96 * BATCH];

// ---------------------------------------------------------------------------
// Kernel 1: cross-Gram blocks. One CTA/element; LDS.128; 31-shfl tree reduce.
// ---------------------------------------------------------------------------
__global__ __launch_bounds__(128)
void gram_kernel(const float* __restrict__ sites) {
    const int b    = blockIdx.x;
    const int tid  = threadIdx.x;
    const int warp = tid >> 5;
    const int lane = tid & 31;

    __shared__ float4 sm4[16 * 64];   // 16 rows x 64 float4 = 16KB

    const float4* S4 = (const float4*)(sites + (size_t)b * (16 * KDIM));
    #pragma unroll
    for (int i = 0; i < 8; i++) sm4[tid + 128 * i] = S4[tid + 128 * i];
    __syncthreads();

    if (warp < 2) {
        // M8 rows i = warp*4 .. warp*4+3 against rows 8..15
        float4 Ar[4][2];
        #pragma unroll
        for (int a = 0; a < 4; a++) {
            Ar[a][0] = sm4[(warp * 4 + a) * 64 + lane];
            Ar[a][1] = sm4[(warp * 4 + a) * 64 + lane + 32];
        }
        float v[32];
        #pragma unroll
        for (int j = 0; j < 8; j++) {
            float4 B0 = sm4[(8 + j) * 64 + lane];
            float4 B1 = sm4[(8 + j) * 64 + lane + 32];
            #pragma unroll
            for (int a = 0; a < 4; a++) {
                float s = 0.f;
                s = fmaf(Ar[a][0].x, B0.x, s); s = fmaf(Ar[a][0].y, B0.y, s);
                s = fmaf(Ar[a][0].z, B0.z, s); s = fmaf(Ar[a][0].w, B0.w, s);
                s = fmaf(Ar[a][1].x, B1.x, s); s = fmaf(Ar[a][1].y, B1.y, s);
                s = fmaf(Ar[a][1].z, B1.z, s); s = fmaf(Ar[a][1].w, B1.w, s);
                v[a * 8 + j] = s;
            }
        }
        // Multi-value tree reduce: 32 sums over 32 lanes in 31 shfl.
        // After: lane l holds the total for output index l in v[0].
        #pragma unroll
        for (int stride = 16; stride >= 1; stride >>= 1) {
            #pragma unroll
            for (int j = 0; j < stride; j++) {
                float send = (lane & stride) ? v[j] : v[j + stride];
                float recv = __shfl_xor_sync(0xffffffffu, send, stride);
                v[j] = ((lane & stride) ? v[j + stride] : v[j]) + recv;
            }
        }
        g_scratch[(warp * 32 + lane) * BATCH + b] = v[0];
    } else {
        // warp2: ML (rows 0-3 x rows 4-7); warp3: MR (rows 8-11 x rows 12-15)
        const int ra   = (warp == 2) ? 0 : 8;
        const int base = (warp == 2) ? 64 : 80;
        float4 Ar[4][2];
        #pragma unroll
        for (int a = 0; a < 4; a++) {
            Ar[a][0] = sm4[(ra + a) * 64 + lane];
            Ar[a][1] = sm4[(ra + a) * 64 + lane + 32];
        }
        float v[16];
        #pragma unroll
        for (int j = 0; j < 4; j++) {
            float4 B0 = sm4[(ra + 4 + j) * 64 + lane];
            float4 B1 = sm4[(ra + 4 + j) * 64 + lane + 32];
            #pragma unroll
            for (int a = 0; a < 4; a++) {
                float s = 0.f;
                s = fmaf(Ar[a][0].x, B0.x, s); s = fmaf(Ar[a][0].y, B0.y, s);
                s = fmaf(Ar[a][0].z, B0.z, s); s = fmaf(Ar[a][0].w, B0.w, s);
                s = fmaf(Ar[a][1].x, B1.x, s); s = fmaf(Ar[a][1].y, B1.y, s);
                s = fmaf(Ar[a][1].z, B1.z, s); s = fmaf(Ar[a][1].w, B1.w, s);
                v[a * 4 + j] = s;
            }
        }
        // Fold upper 16 lanes, then 15-shfl tree over 16 values.
        #pragma unroll
        for (int j = 0; j < 16; j++) v[j] += __shfl_xor_sync(0xffffffffu, v[j], 16);
        #pragma unroll
        for (int stride = 8; stride >= 1; stride >>= 1) {
            #pragma unroll
            for (int j = 0; j < stride; j++) {
                float send = (lane & stride) ? v[j] : v[j + stride];
                float recv = __shfl_xor_sync(0xffffffffu, send, stride);
                v[j] = ((lane & stride) ? v[j + stride] : v[j]) + recv;
            }
        }
        if (lane < 16) g_scratch[(base + lane) * BATCH + b] = v[0];
    }
}

// ---------------------------------------------------------------------------
// Kernel 2: per-thread Jacobi, tournament rounds (4 independent rotations).
// ---------------------------------------------------------------------------
__device__ __forceinline__ void rot_params(float al, float be, float ga,
                                           float& c, float& s) {
    float tau = (be - al) * __fdividef(0.5f, ga);
    float t = copysignf(1.f, tau) *
              __fdividef(1.f, fabsf(tau) + sqrtf(fmaf(tau, tau, 1.f)));
    t = (fabsf(ga) > 1e-30f) ? t : 0.f;
    c = rsqrtf(fmaf(t, t, 1.f));
    s = c * t;
}

__global__ __launch_bounds__(32)
void jacobi_kernel(float* __restrict__ out) {
    // Tournament tables local to the kernel: with full unrolling all indexing
    // is compile-time constant, so these fold into immediates.
    constexpr int P8T[7][4] = {{7,1,2,3},{7,2,3,4},{7,3,4,5},{7,4,5,6},{7,5,6,0},{7,6,0,1},{7,0,1,2}};
    constexpr int Q8T[7][4] = {{0,6,5,4},{1,0,6,5},{2,1,0,6},{3,2,1,0},{4,3,2,1},{5,4,3,2},{6,5,4,3}};
    constexpr int P4T[3][2] = {{3,1},{3,2},{3,0}};
    constexpr int Q4T[3][2] = {{0,2},{1,0},{2,1}};

    const int b = blockIdx.x * 32 + threadIdx.x;

    // ---- 8x8 ----
    float A[8][8];
    #pragma unroll
    for (int o = 0; o < 64; o++) A[o >> 3][o & 7] = g_scratch[o * BATCH + b];

    #pragma unroll 1
    for (int sw = 0; sw < SW8; sw++) {
        #pragma unroll
        for (int r = 0; r < 7; r++) {
            float c[4], s[4];
            #pragma unroll
            for (int g = 0; g < 4; g++) {
                const int p = P8T[r][g], q = Q8T[r][g];
                float al = 0.f, be = 0.f, ga = 0.f;
                #pragma unroll
                for (int k = 0; k < 8; k++) {
                    float u = A[k][p], w = A[k][q];
                    al = fmaf(u, u, al); be = fmaf(w, w, be); ga = fmaf(u, w, ga);
                }
                rot_params(al, be, ga, c[g], s[g]);
            }
            #pragma unroll
            for (int g = 0; g < 4; g++) {
                const int p = P8T[r][g], q = Q8T[r][g];
                #pragma unroll
                for (int k = 0; k < 8; k++) {
                    float u = A[k][p], w = A[k][q];
                    A[k][p] = fmaf(c[g], u, -s[g] * w);
                    A[k][q] = fmaf(s[g], u,  c[g] * w);
                }
            }
        }
    }
    float sq8[8], T8 = 0.f;
    #pragma unroll
    for (int j = 0; j < 8; j++) {
        float v = EPSF;
        #pragma unroll
        for (int k = 0; k < 8; k++) v = fmaf(A[k][j], A[k][j], v);
        sq8[j] = v; T8 += v;
    }
    float invT8 = __fdividef(1.f, T8);
    float H0 = 0.f;
    #pragma unroll
    for (int j = 0; j < 8; j++) {
        float pj = sq8[j] * invT8;
        H0 = fmaf(pj, __logf(pj + EPSF), H0);
    }

    // ---- both 4x4s, interleaved for ILP ----
    // Within a tournament round the two pairs partition {0..3}, so the two
    // rotations on the same matrix touch disjoint columns and commute; params
    // for both are computed from the pre-round matrix (parallel-ordering
    // Jacobi — same scheme that converged to rel_err ~1e-6 in earlier rounds).
    float L[4][4], R[4][4];
    #pragma unroll
    for (int o = 0; o < 16; o++) L[o >> 2][o & 3] = g_scratch[(64 + o) * BATCH + b];
    #pragma unroll
    for (int o = 0; o < 16; o++) R[o >> 2][o & 3] = g_scratch[(80 + o) * BATCH + b];

    #pragma unroll 1
    for (int sw = 0; sw < SW4; sw++) {
        #pragma unroll
        for (int r = 0; r < 3; r++) {
            float c[4], s[4];
            #pragma unroll
            for (int g = 0; g < 4; g++) {
                const int p = P4T[r][g & 1], q = Q4T[r][g & 1];
                float (*M)[4] = (g < 2) ? L : R;
                float al = 0.f, be = 0.f, ga = 0.f;
                #pragma unroll
                for (int k = 0; k < 4; k++) {
                    float u = M[k][p], w = M[k][q];
                    al = fmaf(u, u, al); be = fmaf(w, w, be); ga = fmaf(u, w, ga);
                }
                rot_params(al, be, ga, c[g], s[g]);
            }
            #pragma unroll
            for (int g = 0; g < 4; g++) {
                const int p = P4T[r][g & 1], q = Q4T[r][g & 1];
                float (*M)[4] = (g < 2) ? L : R;
                #pragma unroll
                for (int k = 0; k < 4; k++) {
                    float u = M[k][p], w = M[k][q];
                    M[k][p] = fmaf(c[g], u, -s[g] * w);
                    M[k][q] = fmaf(s[g], u,  c[g] * w);
                }
            }
        }
    }

    float H1 = 0.f, H2 = 0.f;
    {
        float sq[4], T = 0.f;
        #pragma unroll
        for (int j = 0; j < 4; j++) {
            float v = EPSF;
            #pragma unroll
            for (int k = 0; k < 4; k++) v = fmaf(L[k][j], L[k][j], v);
            sq[j] = v; T += v;
        }
        float invT = __fdividef(1.f, T);
        #pragma unroll
        for (int j = 0; j < 4; j++) {
            float pj = sq[j] * invT;
            H1 = fmaf(pj, __logf(pj + EPSF), H1);
        }
    }
    {
        float sq[4], T = 0.f;
        #pragma unroll
        for (int j = 0; j < 4; j++) {
            float v = EPSF;
            #pragma unroll
            for (int k = 0; k < 4; k++) v = fmaf(R[k][j], R[k][j], v);
            sq[j] = v; T += v;
        }
        float invT = __fdividef(1.f, T);
        #pragma unroll
        for (int j = 0; j < 4; j++) {
            float pj = sq[j] * invT;
            H2 = fmaf(pj, __logf(pj + EPSF), H2);
        }
    }

    // H = -sum; phi = (-H0) - (-H1) - (-H2)
    float phi = (-H0) + H1 + H2;
    out[b] = phi > 0.f ? phi : 0.f;
}

extern "C" void kernel_launch(void* const* d_in, const int* in_sizes, int n_in,
                              void* d_out, int out_size) {
    const float* sites = (const float*)d_in[0];
    float* out = (float*)d_out;
    gram_kernel<<<BATCH, 128>>>(sites);
    jacobi_kernel<<<BATCH / 32, 32>>>(out);
}

// round 7
// speedup vs baseline: 6.3140x; 1.5626x over previous
#include <cuda_runtime.h>

#define BATCH   8192
#define KDIM    256
#define EPSF    1e-10f
#define SW8     4
#define SW4     3

// Packed fp32x2 FMA (Blackwell): only reachable via PTX.
#define FMA_F32X2(d, a, b, c) \
    asm("fma.rn.f32x2 %0, %1, %2, %3;" : "=l"(d) : "l"(a), "l"(b), "l"(c))
#define UNPACK_F32X2(lo, hi, in) do {                                   \
    unsigned _ulo, _uhi;                                                \
    asm("mov.b64 {%0, %1}, %2;" : "=r"(_ulo), "=r"(_uhi) : "l"(in));    \
    lo = __uint_as_float(_ulo); hi = __uint_as_float(_uhi);             \
} while (0)

// Scratch, element-major [BATCH][96]:
// 0..63  -> M8[i][j] = dot(row i,   row 8+j)   (o = i*8+j)
// 64..79 -> ML[i][j] = dot(row i,   row 4+j)
// 80..95 -> MR[i][j] = dot(row 8+i, row 12+j)
__device__ float g_scratch[BATCH * 96];

// ---------------------------------------------------------------------------
// Kernel 1: cross-Gram blocks. One CTA/element. No smem: direct LDG.128
// (L1 catches cross-warp row reuse). Dots accumulated in packed f32x2.
// ---------------------------------------------------------------------------
__global__ __launch_bounds__(128)
void gram_kernel(const float* __restrict__ sites) {
    const int b    = blockIdx.x;
    const int tid  = threadIdx.x;
    const int warp = tid >> 5;
    const int lane = tid & 31;

    // Row r = 256 floats = 64 x 16B. Lane owns chunks (lane) and (lane+32).
    const ulonglong2* S2 = (const ulonglong2*)(sites + (size_t)b * (16 * KDIM));

    if (warp < 2) {
        // M8 rows i = warp*4..warp*4+3 vs rows 8..15 -> 32 outputs
        ulonglong2 Ar[4][2];
        #pragma unroll
        for (int a = 0; a < 4; a++) {
            Ar[a][0] = S2[(warp * 4 + a) * 64 + lane];
            Ar[a][1] = S2[(warp * 4 + a) * 64 + lane + 32];
        }
        unsigned long long acc[32];
        #pragma unroll
        for (int o = 0; o < 32; o++) acc[o] = 0ull;  // (0.f,0.f)

        #pragma unroll
        for (int j = 0; j < 8; j++) {
            ulonglong2 B0 = S2[(8 + j) * 64 + lane];
            ulonglong2 B1 = S2[(8 + j) * 64 + lane + 32];
            #pragma unroll
            for (int a = 0; a < 4; a++) {
                unsigned long long& d = acc[a * 8 + j];
                FMA_F32X2(d, Ar[a][0].x, B0.x, d);
                FMA_F32X2(d, Ar[a][0].y, B0.y, d);
                FMA_F32X2(d, Ar[a][1].x, B1.x, d);
                FMA_F32X2(d, Ar[a][1].y, B1.y, d);
            }
        }
        float v[32];
        #pragma unroll
        for (int o = 0; o < 32; o++) {
            float lo, hi; UNPACK_F32X2(lo, hi, acc[o]);
            v[o] = lo + hi;
        }
        // Multi-value tree reduce: 32 lane-sums in 31 shfl; lane l ends with out l.
        #pragma unroll
        for (int stride = 16; stride >= 1; stride >>= 1) {
            #pragma unroll
            for (int j = 0; j < stride; j++) {
                float send = (lane & stride) ? v[j] : v[j + stride];
                float recv = __shfl_xor_sync(0xffffffffu, send, stride);
                v[j] = ((lane & stride) ? v[j + stride] : v[j]) + recv;
            }
        }
        g_scratch[b * 96 + warp * 32 + lane] = v[0];
    } else {
        // warp2: ML (rows 0-3 x 4-7); warp3: MR (rows 8-11 x 12-15) -> 16 outputs
        const int ra   = (warp == 2) ? 0 : 8;
        const int base = (warp == 2) ? 64 : 80;
        ulonglong2 Ar[4][2];
        #pragma unroll
        for (int a = 0; a < 4; a++) {
            Ar[a][0] = S2[(ra + a) * 64 + lane];
            Ar[a][1] = S2[(ra + a) * 64 + lane + 32];
        }
        unsigned long long acc[16];
        #pragma unroll
        for (int o = 0; o < 16; o++) acc[o] = 0ull;

        #pragma unroll
        for (int j = 0; j < 4; j++) {
            ulonglong2 B0 = S2[(ra + 4 + j) * 64 + lane];
            ulonglong2 B1 = S2[(ra + 4 + j) * 64 + lane + 32];
            #pragma unroll
            for (int a = 0; a < 4; a++) {
                unsigned long long& d = acc[a * 4 + j];
                FMA_F32X2(d, Ar[a][0].x, B0.x, d);
                FMA_F32X2(d, Ar[a][0].y, B0.y, d);
                FMA_F32X2(d, Ar[a][1].x, B1.x, d);
                FMA_F32X2(d, Ar[a][1].y, B1.y, d);
            }
        }
        float v[16];
        #pragma unroll
        for (int o = 0; o < 16; o++) {
            float lo, hi; UNPACK_F32X2(lo, hi, acc[o]);
            v[o] = lo + hi;
        }
        #pragma unroll
        for (int j = 0; j < 16; j++) v[j] += __shfl_xor_sync(0xffffffffu, v[j], 16);
        #pragma unroll
        for (int stride = 8; stride >= 1; stride >>= 1) {
            #pragma unroll
            for (int j = 0; j < stride; j++) {
                float send = (lane & stride) ? v[j] : v[j + stride];
                float recv = __shfl_xor_sync(0xffffffffu, send, stride);
                v[j] = ((lane & stride) ? v[j + stride] : v[j]) + recv;
            }
        }
        if (lane < 16) g_scratch[b * 96 + base + lane] = v[0];
    }
}

// ---------------------------------------------------------------------------
// Kernel 2: 8 lanes per element; one column per lane (one-sided Jacobi).
// Role-symmetric rotation: each lane uses al=own norm, be=partner norm and
// applies a' = c*a - s*b; tau negation on the partner lane reproduces the
// q-formula exactly, and gamma is bit-identical on both lanes.
// ---------------------------------------------------------------------------
__device__ __forceinline__ void rot_params(float al, float be, float ga,
                                           float& c, float& s) {
    float tau = (be - al) * __fdividef(0.5f, ga);
    float t = copysignf(1.f, tau) *
              __fdividef(1.f, fabsf(tau) + sqrtf(fmaf(tau, tau, 1.f)));
    t = (fabsf(ga) > 1e-30f) ? t : 0.f;
    c = rsqrtf(fmaf(t, t, 1.f));
    s = c * t;
}

__global__ __launch_bounds__(128)
void jacobi_kernel(float* __restrict__ out) {
    const unsigned FULL = 0xffffffffu;
    const int tid = threadIdx.x;
    const int j   = tid & 7;                        // my column (8x8)
    const int b   = blockIdx.x * 16 + (tid >> 3);   // element
    const float* base = g_scratch + b * 96;

    // ---- 8x8 ----
    float a[8];
    #pragma unroll
    for (int k = 0; k < 8; k++) a[k] = base[k * 8 + j];

    #pragma unroll 1
    for (int sw = 0; sw < SW8; sw++) {
        #pragma unroll
        for (int r = 0; r < 7; r++) {
            // round-robin pairing: (7,r) and ((r+i)%7,(r+7-i)%7)
            int partner = (j == r) ? 7 : ((j == 7) ? r : ((2 * r + 14 - j) % 7));
            float n = 0.f;
            #pragma unroll
            for (int k = 0; k < 8; k++) n = fmaf(a[k], a[k], n);
            float bc[8];
            #pragma unroll
            for (int k = 0; k < 8; k++) bc[k] = __shfl_sync(FULL, a[k], partner, 8);
            float bn = __shfl_sync(FULL, n, partner, 8);
            float ga = 0.f;
            #pragma unroll
            for (int k = 0; k < 8; k++) ga = fmaf(a[k], bc[k], ga);
            float c, s;
            rot_params(n, bn, ga, c, s);
            #pragma unroll
            for (int k = 0; k < 8; k++) a[k] = fmaf(c, a[k], -s * bc[k]);
        }
    }
    // entropy of column norms^2
    float sq8 = EPSF;
    #pragma unroll
    for (int k = 0; k < 8; k++) sq8 = fmaf(a[k], a[k], sq8);
    float T8 = sq8;
    #pragma unroll
    for (int m = 4; m >= 1; m >>= 1) T8 += __shfl_xor_sync(FULL, T8, m, 8);
    float p8 = sq8 * __fdividef(1.f, T8);
    float s8 = p8 * __logf(p8 + EPSF);
    #pragma unroll
    for (int m = 4; m >= 1; m >>= 1) s8 += __shfl_xor_sync(FULL, s8, m, 8);
    // S_whole = -s8 (all 8 lanes agree)

    // ---- both 4x4s: lanes 0-3 -> ML, lanes 4-7 -> MR, width-4 shuffles ----
    const int j4  = j & 3;
    const int isR = j >> 2;
    const float* mb = base + 64 + isR * 16;
    float m4[4];
    #pragma unroll
    for (int k = 0; k < 4; k++) m4[k] = mb[k * 4 + j4];

    #pragma unroll 1
    for (int sw = 0; sw < SW4; sw++) {
        #pragma unroll
        for (int r = 0; r < 3; r++) {
            int partner = (j4 == r) ? 3 : ((j4 == 3) ? r : ((2 * r + 6 - j4) % 3));
            float n = 0.f;
            #pragma unroll
            for (int k = 0; k < 4; k++) n = fmaf(m4[k], m4[k], n);
            float bc[4];
            #pragma unroll
            for (int k = 0; k < 4; k++) bc[k] = __shfl_sync(FULL, m4[k], partner, 4);
            float bn = __shfl_sync(FULL, n, partner, 4);
            float ga = 0.f;
            #pragma unroll
            for (int k = 0; k < 4; k++) ga = fmaf(m4[k], bc[k], ga);
            float c, s;
            rot_params(n, bn, ga, c, s);
            #pragma unroll
            for (int k = 0; k < 4; k++) m4[k] = fmaf(c, m4[k], -s * bc[k]);
        }
    }
    float sq4 = EPSF;
    #pragma unroll
    for (int k = 0; k < 4; k++) sq4 = fmaf(m4[k], m4[k], sq4);
    float T4 = sq4;
    #pragma unroll
    for (int m = 2; m >= 1; m >>= 1) T4 += __shfl_xor_sync(FULL, T4, m, 4);
    float p4 = sq4 * __fdividef(1.f, T4);
    float s4 = p4 * __logf(p4 + EPSF);
    #pragma unroll
    for (int m = 2; m >= 1; m >>= 1) s4 += __shfl_xor_sync(FULL, s4, m, 4);
    // lanes 0-3 hold sum for ML, lanes 4-7 for MR

    float s4R = __shfl_sync(FULL, s4, 4, 8);   // lane 0 reads MR's sum from lane 4
    if (j == 0) {
        // phi = S_whole - S_left - S_right = -s8 + s4(L) + s4(R)
        float phi = -s8 + s4 + s4R;
        out[b] = phi > 0.f ? phi : 0.f;
    }
}

extern "C" void kernel_launch(void* const* d_in, const int* in_sizes, int n_in,
                              void* d_out, int out_size) {
    const float* sites = (const float*)d_in[0];
    float* out = (float*)d_out;
    gram_kernel<<<BATCH, 128>>>(sites);
    jacobi_kernel<<<BATCH / 16, 128>>>(out);
}